// round 4
// baseline (speedup 1.0000x reference)
#include <cuda_runtime.h>
#include <cuda_bf16.h>

// ---------------------------------------------------------------------------
// LatentLayer loss, factorized, single fused kernel (R3):
//   exp(alpha*d_ij) = G[i,k] * H[i,m] * exp(alpha*|e_j|^2),  j = k*1024 + m
//   C[k,m] = sum_i G[i,k]*H[i,m]
//   lse_j  = alpha*|e_j|^2 + ln(C[k,m])
//   loss   = -mean(lse) + (2*ls - 1) + ln(N)
// Grid: 148 CTAs x 512 threads, one CTA per SM, single wave.
// Each CTA owns a K-slice of 56 rows; each thread owns 2 m-columns x 16 k.
// Cross-CTA reduction via red.global.add.v2.f32 (148 contributions/address).
// Last-arriving CTA computes the lse reduction and resets state for replay.
// ---------------------------------------------------------------------------

#define N_Z      8192
#define M_EPS    1024
#define N_EMB    16
#define NBLK     148
#define NTHR     512
#define CHUNK    56        // 148*56 = 8288 >= 8192
#define M_TOT    (N_EMB * M_EPS)   // 16384

__device__ __align__(16) float g_C[M_TOT];   // zero-initialized .bss
__device__ unsigned int g_done = 0;

__device__ __forceinline__ float ex2f(float x) {
    float y; asm("ex2.approx.ftz.f32 %0, %1;" : "=f"(y) : "f"(x)); return y;
}
__device__ __forceinline__ float lg2f(float x) {
    float y; asm("lg2.approx.ftz.f32 %0, %1;" : "=f"(y) : "f"(x)); return y;
}
__device__ __forceinline__ unsigned long long pack2(float lo, float hi) {
    unsigned long long r;
    asm("mov.b64 %0, {%1, %2};" : "=l"(r) : "f"(lo), "f"(hi));
    return r;
}
__device__ __forceinline__ void unpack2(unsigned long long v, float& lo, float& hi) {
    asm("mov.b64 {%0, %1}, %2;" : "=f"(lo), "=f"(hi) : "l"(v));
}
__device__ __forceinline__ unsigned long long fma2(unsigned long long a,
                                                   unsigned long long b,
                                                   unsigned long long c) {
    unsigned long long d;
    asm("fma.rn.f32x2 %0, %1, %2, %3;" : "=l"(d) : "l"(a), "l"(b), "l"(c));
    return d;
}
__device__ __forceinline__ unsigned long long mul2(unsigned long long a,
                                                   unsigned long long b) {
    unsigned long long d;
    asm("mul.rn.f32x2 %0, %1, %2;" : "=l"(d) : "l"(a), "l"(b));
    return d;
}

__global__ __launch_bounds__(NTHR, 1)
void fused_kernel(const float* __restrict__ z,
                  const float* __restrict__ emb,
                  const float* __restrict__ lsig,
                  const float* __restrict__ eps,
                  const float* __restrict__ temp,
                  float* __restrict__ out)
{
    __shared__ float2 sGd[CHUNK][N_EMB];  // G duplicated: (g, g) pairs
    __shared__ float2 sZ[CHUNK];          // pre-scaled z: LOG2E*u*T*z_i
    __shared__ float  sred[NTHR];
    __shared__ int    sIsLast;

    const int   tid = threadIdx.x;
    const float T   = temp[0];
    const float ls  = lsig[0];
    const float u   = __expf(-2.0f * ls);       // 1/sigma^2
    const float alpha = -0.5f * u;
    const float L2E = 1.4426950408889634f;
    const float LN2 = 0.6931471805599453f;

    const int i0 = blockIdx.x * CHUNK;

    // --- prologue: G[i][k] duplicated, scaled z in smem ---
    for (int t = tid; t < CHUNK * N_EMB; t += NTHR) {
        int il = t >> 4;
        int k  = t & 15;
        int i  = i0 + il;
        float g = 0.0f;
        if (i < N_Z) {
            float zx = z[2 * i], zy = z[2 * i + 1];
            float mx = (1.0f - T) * emb[2 * k];
            float my = (1.0f - T) * emb[2 * k + 1];
            float a  = alpha * (zx * zx + zy * zy) + u * (zx * mx + zy * my);
            g = ex2f(L2E * a);
        }
        sGd[il][k] = make_float2(g, g);
    }
    if (tid < CHUNK) {
        int i = i0 + tid;
        float s  = L2E * u * T;
        float zx = (i < N_Z) ? z[2 * i]     : 0.0f;
        float zy = (i < N_Z) ? z[2 * i + 1] : 0.0f;
        sZ[tid] = make_float2(s * zx, s * zy);
    }
    __syncthreads();

    // --- per-thread pair of m-columns, rotated per block to spread LTS load ---
    const int mbase = 2 * ((tid + blockIdx.x) & (NTHR - 1));

    // eps columns m, m+1: (x0,y0,x1,y1) -> epx=(x0,x1), epy=(y0,y1)
    float4 q = *reinterpret_cast<const float4*>(&eps[2 * mbase]);
    const unsigned long long epx = pack2(q.x, q.z);
    const unsigned long long epy = pack2(q.y, q.w);

    unsigned long long acc[N_EMB];
#pragma unroll
    for (int k = 0; k < N_EMB; k++) acc[k] = 0ull;

    // --- main loop: 16 independent fma2 chains + 2 MUFU + 4 LDS.128 / iter ---
#pragma unroll 2
    for (int il = 0; il < CHUNK; il++) {
        float2 zz = sZ[il];
        unsigned long long zx2 = pack2(zz.x, zz.x);
        unsigned long long zy2 = pack2(zz.y, zz.y);
        unsigned long long ha = fma2(zx2, epx, mul2(zy2, epy));
        float a0, a1;
        unpack2(ha, a0, a1);
        unsigned long long h01 = pack2(ex2f(a0), ex2f(a1));

#pragma unroll
        for (int k2 = 0; k2 < N_EMB / 2; k2++) {
            ulonglong2 gg = *reinterpret_cast<const ulonglong2*>(&sGd[il][2 * k2]);
            acc[2 * k2]     = fma2(gg.x, h01, acc[2 * k2]);
            acc[2 * k2 + 1] = fma2(gg.y, h01, acc[2 * k2 + 1]);
        }
    }

    // --- epilogue: vector reductions into global C (2 floats per k) ---
#pragma unroll
    for (int k = 0; k < N_EMB; k++) {
        float c0, c1;
        unpack2(acc[k], c0, c1);
        asm volatile("red.global.add.v2.f32 [%0], {%1, %2};"
                     :: "l"(&g_C[k * M_EPS + mbase]), "f"(c0), "f"(c1)
                     : "memory");
    }
    __threadfence();

    if (tid == 0) {
        unsigned int ticket = atomicAdd(&g_done, 1u);
        sIsLast = (ticket == NBLK - 1);
    }
    __syncthreads();
    if (!sIsLast) return;

    // ===== last block: lse over all 16384 columns, reduce, finalize =====
    __threadfence();   // acquire: observe all red results
    float sum = 0.0f;
#pragma unroll
    for (int q2 = 0; q2 < M_TOT / NTHR; q2++) {
        int j = q2 * NTHR + tid;
        int k = j >> 10;
        int m = j & 1023;
        float ex = (1.0f - T) * emb[2 * k]     + T * eps[2 * m];
        float ey = (1.0f - T) * emb[2 * k + 1] + T * eps[2 * m + 1];
        float c  = g_C[j];
        g_C[j] = 0.0f;    // reset for next replay
        sum += alpha * (ex * ex + ey * ey) + lg2f(c) * LN2;
    }
    sred[tid] = sum;
    __syncthreads();
#pragma unroll
    for (int s = NTHR / 2; s > 0; s >>= 1) {
        if (tid < s) sred[tid] += sred[tid + s];
        __syncthreads();
    }
    if (tid == 0) {
        g_done = 0;       // reset counter for next replay
        out[0] = -sred[0] / (float)M_TOT + (2.0f * ls - 1.0f) + logf((float)N_Z);
    }
}

// ---------------------------------------------------------------------------
extern "C" void kernel_launch(void* const* d_in, const int* in_sizes, int n_in,
                              void* d_out, int out_size)
{
    const float* z    = (const float*)d_in[0];
    const float* emb  = (const float*)d_in[1];
    const float* lsig = (const float*)d_in[2];
    const float* eps  = (const float*)d_in[3];
    const float* temp = (const float*)d_in[4];
    float* out = (float*)d_out;

    fused_kernel<<<NBLK, NTHR>>>(z, emb, lsig, eps, temp, out);
}

// round 6
// speedup vs baseline: 1.2821x; 1.2821x over previous
#include <cuda_runtime.h>
#include <cuda_bf16.h>

// ---------------------------------------------------------------------------
// LatentLayer loss, factorized, single fused kernel (R4):
//   exp(alpha*d_ij) = G[i,k] * H[i,m] * exp(alpha*|e_j|^2),  j = k*1024 + m
//   C[k,m] = sum_i G[i,k]*H[i,m]      (f32x2 FFMA GEMM, K=8192, out 16x1024)
//   lse_j  = alpha*|e_j|^2 + ln(C[k,m])
//   loss   = -mean(lse) + (2*ls - 1) + ln(N)
// Grid: 296 CTAs x 256 thr (2 CTAs/SM).  Thread owns 4 m-cols x all 16 k.
// Main loop software-pipelines the H chain (LDS->FFMA->MUFU->pack) one
// iteration ahead so the 32 acc FMAs never wait on it.
// Sum_j alpha*|e_j|^2 is computed in closed form in the tail.
// ---------------------------------------------------------------------------

#define N_Z      8192
#define M_EPS    1024
#define N_EMB    16
#define NBLK     296
#define NTHR     256
#define CHUNK    28        // 296*28 = 8288 >= 8192
#define M_TOT    (N_EMB * M_EPS)   // 16384

__device__ __align__(16) float g_C[M_TOT];   // zero-initialized .bss
__device__ unsigned int g_done = 0;

__device__ __forceinline__ float ex2f(float x) {
    float y; asm("ex2.approx.ftz.f32 %0, %1;" : "=f"(y) : "f"(x)); return y;
}
__device__ __forceinline__ float lg2f(float x) {
    float y; asm("lg2.approx.ftz.f32 %0, %1;" : "=f"(y) : "f"(x)); return y;
}
__device__ __forceinline__ unsigned long long pack2(float lo, float hi) {
    unsigned long long r;
    asm("mov.b64 %0, {%1, %2};" : "=l"(r) : "f"(lo), "f"(hi));
    return r;
}
__device__ __forceinline__ void unpack2(unsigned long long v, float& lo, float& hi) {
    asm("mov.b64 {%0, %1}, %2;" : "=f"(lo), "=f"(hi) : "l"(v));
}
__device__ __forceinline__ unsigned long long fma2(unsigned long long a,
                                                   unsigned long long b,
                                                   unsigned long long c) {
    unsigned long long d;
    asm("fma.rn.f32x2 %0, %1, %2, %3;" : "=l"(d) : "l"(a), "l"(b), "l"(c));
    return d;
}

__global__ __launch_bounds__(NTHR, 2)
void fused_kernel(const float* __restrict__ z,
                  const float* __restrict__ emb,
                  const float* __restrict__ lsig,
                  const float* __restrict__ eps,
                  const float* __restrict__ temp,
                  float* __restrict__ out)
{
    __shared__ __align__(16) float2 sGd[CHUNK][N_EMB];  // (g,g) pairs
    __shared__ float2 sZ[CHUNK + 1];   // pre-scaled z; entry CHUNK = pad
    __shared__ float4 sred[NTHR];
    __shared__ int    sIsLast;

    const int   tid = threadIdx.x;
    const float T   = temp[0];
    const float ls  = lsig[0];
    const float u   = __expf(-2.0f * ls);       // 1/sigma^2
    const float alpha = -0.5f * u;
    const float L2E = 1.4426950408889634f;
    const float LN2 = 0.6931471805599453f;

    const int i0 = blockIdx.x * CHUNK;

    // --- prologue: G[i][k] duplicated, scaled z in smem ---
    for (int t = tid; t < CHUNK * N_EMB; t += NTHR) {
        int il = t >> 4;
        int k  = t & 15;
        int i  = i0 + il;
        float g = 0.0f;
        if (i < N_Z) {
            float zx = z[2 * i], zy = z[2 * i + 1];
            float mx = (1.0f - T) * emb[2 * k];
            float my = (1.0f - T) * emb[2 * k + 1];
            float a  = alpha * (zx * zx + zy * zy) + u * (zx * mx + zy * my);
            g = ex2f(L2E * a);
        }
        sGd[il][k] = make_float2(g, g);
    }
    if (tid <= CHUNK) {
        int i = i0 + tid;
        float s  = L2E * u * T;
        float zx = (tid < CHUNK && i < N_Z) ? z[2 * i]     : 0.0f;
        float zy = (tid < CHUNK && i < N_Z) ? z[2 * i + 1] : 0.0f;
        sZ[tid] = make_float2(s * zx, s * zy);
    }
    __syncthreads();

    // --- per-thread columns, rotated per block to spread LTS traffic ---
    const int mbase = 4 * ((tid + blockIdx.x) & 255);

    float4 q0 = *reinterpret_cast<const float4*>(&eps[2 * mbase]);      // x0,y0,x1,y1
    float4 q1 = *reinterpret_cast<const float4*>(&eps[2 * mbase + 4]);  // x2,y2,x3,y3
    const float ep0x = q0.x, ep0y = q0.y, ep1x = q0.z, ep1y = q0.w;
    const float ep2x = q1.x, ep2y = q1.y, ep3x = q1.z, ep3y = q1.w;

    unsigned long long acc01[N_EMB], acc23[N_EMB];
#pragma unroll
    for (int k = 0; k < N_EMB; k++) { acc01[k] = 0ull; acc23[k] = 0ull; }

    // --- prime the H pipeline for il = 0 ---
    unsigned long long h01, h23;
    {
        float2 zz = sZ[0];
        float b0 = fmaf(zz.x, ep0x, zz.y * ep0y);
        float b1 = fmaf(zz.x, ep1x, zz.y * ep1y);
        float b2 = fmaf(zz.x, ep2x, zz.y * ep2y);
        float b3 = fmaf(zz.x, ep3x, zz.y * ep3y);
        h01 = pack2(ex2f(b0), ex2f(b1));
        h23 = pack2(ex2f(b2), ex2f(b3));
    }

    // --- main loop: compute next H first (independent), then 32 acc fma2 ---
#pragma unroll 1
    for (int il = 0; il < CHUNK; il++) {
        // next-iteration H chain (hides LDS/MUFU latency under the accs)
        float2 zzn = sZ[il + 1];
        float b0 = fmaf(zzn.x, ep0x, zzn.y * ep0y);
        float b1 = fmaf(zzn.x, ep1x, zzn.y * ep1y);
        float b2 = fmaf(zzn.x, ep2x, zzn.y * ep2y);
        float b3 = fmaf(zzn.x, ep3x, zzn.y * ep3y);
        float e0 = ex2f(b0), e1 = ex2f(b1), e2 = ex2f(b2), e3 = ex2f(b3);

#pragma unroll
        for (int q = 0; q < N_EMB / 2; q++) {
            ulonglong2 gg = *reinterpret_cast<const ulonglong2*>(&sGd[il][2 * q]);
            acc01[2 * q]     = fma2(gg.x, h01, acc01[2 * q]);
            acc23[2 * q]     = fma2(gg.x, h23, acc23[2 * q]);
            acc01[2 * q + 1] = fma2(gg.y, h01, acc01[2 * q + 1]);
            acc23[2 * q + 1] = fma2(gg.y, h23, acc23[2 * q + 1]);
        }
        h01 = pack2(e0, e1);
        h23 = pack2(e2, e3);
    }

    // --- epilogue: vector reductions into global C ---
#pragma unroll
    for (int k = 0; k < N_EMB; k++) {
        float c0, c1, c2, c3;
        unpack2(acc01[k], c0, c1);
        unpack2(acc23[k], c2, c3);
        asm volatile("red.global.add.v4.f32 [%0], {%1, %2, %3, %4};"
                     :: "l"(&g_C[k * M_EPS + mbase]),
                        "f"(c0), "f"(c1), "f"(c2), "f"(c3)
                     : "memory");
    }
    __threadfence();

    if (tid == 0) {
        unsigned int ticket = atomicAdd(&g_done, 1u);
        sIsLast = (ticket == NBLK - 1);
    }
    __syncthreads();
    if (!sIsLast) return;

    // ===== last block: tail =====
    __threadfence();   // acquire: observe all red results

    // (a) sum of lg2(C) over all 16384 columns, float4 loads, zero-store
    float lgsum = 0.0f;
#pragma unroll
    for (int q = 0; q < M_TOT / (4 * NTHR); q++) {     // 16 iters
        int j4 = (q * NTHR + tid);
        float4 c = reinterpret_cast<float4*>(g_C)[j4];
        reinterpret_cast<float4*>(g_C)[j4] = make_float4(0.f, 0.f, 0.f, 0.f);
        lgsum += lg2f(c.x) + lg2f(c.y) + lg2f(c.z) + lg2f(c.w);
    }

    // (b) closed-form Sum_j |e_j|^2:
    //   = 1024*Sum_k|mk|^2 + 2T*(Sum_k mk)·(Sum_m em) + 16*T^2*Sum_m|em|^2
    float sx = 0.f, sy = 0.f, ss = 0.f;
#pragma unroll
    for (int q = 0; q < M_EPS / NTHR; q++) {           // 4 m per thread
        int m = q * NTHR + tid;
        float2 e = reinterpret_cast<const float2*>(eps)[m];
        sx += e.x; sy += e.y; ss += e.x * e.x + e.y * e.y;
    }

    sred[tid] = make_float4(lgsum, sx, sy, ss);
    __syncthreads();
#pragma unroll
    for (int s = NTHR / 2; s > 0; s >>= 1) {
        if (tid < s) {
            float4 a = sred[tid], b = sred[tid + s];
            sred[tid] = make_float4(a.x + b.x, a.y + b.y, a.z + b.z, a.w + b.w);
        }
        __syncthreads();
    }
    if (tid == 0) {
        float4 r = sred[0];
        float mkx = 0.f, mky = 0.f, mk2 = 0.f;
        for (int k = 0; k < N_EMB; k++) {
            float mx = (1.0f - T) * emb[2 * k];
            float my = (1.0f - T) * emb[2 * k + 1];
            mkx += mx; mky += my; mk2 += mx * mx + my * my;
        }
        float Se = (float)M_EPS * mk2
                 + 2.0f * T * (mkx * r.y + mky * r.z)
                 + (float)N_EMB * T * T * r.w;
        float sum_lse = alpha * Se + LN2 * r.x;
        g_done = 0;       // reset counter for next replay
        out[0] = -sum_lse / (float)M_TOT + (2.0f * ls - 1.0f) + logf((float)N_Z);
    }
}

// ---------------------------------------------------------------------------
extern "C" void kernel_launch(void* const* d_in, const int* in_sizes, int n_in,
                              void* d_out, int out_size)
{
    const float* z    = (const float*)d_in[0];
    const float* emb  = (const float*)d_in[1];
    const float* lsig = (const float*)d_in[2];
    const float* eps  = (const float*)d_in[3];
    const float* temp = (const float*)d_in[4];
    float* out = (float*)d_out;

    fused_kernel<<<NBLK, NTHR>>>(z, emb, lsig, eps, temp, out);
}